// round 6
// baseline (speedup 1.0000x reference)
#include <cuda_runtime.h>
#include <cuda_bf16.h>
#include <stdint.h>

// LUT_82085414961764: out = a[idx]*d + b[idx], idx = searchsorted(x, d, 'left')
//
// Fused-bin scheme: fused[NB] float2 entries.
//   empty bin  -> entry = (a[lo], b[lo])          : 1 LDS.64 + FFMA, done.
//   flagged bin-> entry.x = tag(0x7F800000) | lo  : scan x_s from lo, gather ab_s.
// Tag uses the all-ones exponent pattern (Inf/NaN); a is a finite random normal
// so real entries never match. Bin function g() is the IDENTICAL monotone float
// expression at build and query time -> lo is a provably correct lower bound.

#define KMAX 1024
#define NB   8192

// dynamic smem layout (bytes): fused[NB] | x_s[KMAX] | ab_s[KMAX+1]
#define FUSED_BYTES (NB * 8)
#define XS_BYTES    (KMAX * 4)
#define AB_BYTES    ((KMAX + 1) * 8)
#define SMEM_BYTES  (FUSED_BYTES + XS_BYTES + AB_BYTES)

__global__ __launch_bounds__(512, 2)
void lut_kernel(const float* __restrict__ data,
                const float* __restrict__ x,
                const float* __restrict__ a,
                const float* __restrict__ b,
                float* __restrict__ out,
                int K, long long n)
{
    extern __shared__ char smem[];
    float2*  fused = (float2*)smem;
    float*   x_s   = (float*)(smem + FUSED_BYTES);
    float2*  ab_s  = (float2*)(smem + FUSED_BYTES + XS_BYTES);

    const int tid = threadIdx.x;
    const int bd  = blockDim.x;

    // ---- build phase ----------------------------------------------------
    for (int i = tid; i < K; i += bd)  x_s[i] = x[i];
    for (int i = tid; i <= K; i += bd) ab_s[i] = make_float2(a[i], b[i]);
    __syncthreads();

    const float LO    = x_s[0];
    const float span  = x_s[K - 1] - LO;
    const float scale = (span > 0.0f) ? ((float)NB / span) : 0.0f;
    const float NBf   = (float)NB;

    // monotone bin function — identical expression at build and query
    auto g = [&](float v) -> int {
        float t = (v - LO) * scale;
        if (t < 0.0f) return 0;
        if (t >= NBf) return NB - 1;
        return (int)t;
    };

    for (int bin = tid; bin < NB; bin += bd) {
        int lo = 0, hi = K;
        while (lo < hi) {
            int mid = (lo + hi) >> 1;
            if (g(x_s[mid]) < bin) lo = mid + 1; else hi = mid;
        }
        float2 e;
        if (lo < K && g(x_s[lo]) == bin) {
            // flagged: tag + start index in mantissa
            e.x = __uint_as_float(0x7F800000u | (unsigned)lo);
            e.y = 0.0f;
        } else {
            e = ab_s[lo];   // lo may be K: ab_s[K] is valid
        }
        fused[bin] = e;
    }
    __syncthreads();

    // ---- streaming phase -------------------------------------------------
    auto lut1 = [&](float d) -> float {
        float t = (d - LO) * scale;
        int bin;
        if (t < 0.0f)      bin = 0;
        else if (t >= NBf) bin = NB - 1;
        else               bin = (int)t;
        float2 e = fused[bin];
        unsigned ux = __float_as_uint(e.x);
        if ((ux & 0x7F800000u) == 0x7F800000u) {
            int idx = (int)(ux & 0x7FFFu);
            while (idx < K && x_s[idx] < d) ++idx;
            e = ab_s[idx];
        }
        return fmaf(e.x, d, e.y);
    };

    const long long n4 = n >> 2;
    const float4* __restrict__ in4  = (const float4*)data;
    float4* __restrict__       out4 = (float4*)out;
    const long long stride = (long long)gridDim.x * bd;

    for (long long i = (long long)blockIdx.x * bd + tid; i < n4; i += stride) {
        float4 v = in4[i];
        float4 r;
        r.x = lut1(v.x);
        r.y = lut1(v.y);
        r.z = lut1(v.z);
        r.w = lut1(v.w);
        out4[i] = r;
    }

    for (long long i = (n4 << 2) + (long long)blockIdx.x * bd + tid; i < n;
         i += stride) {
        out[i] = lut1(data[i]);
    }
}

extern "C" void kernel_launch(void* const* d_in, const int* in_sizes, int n_in,
                              void* d_out, int out_size)
{
    const float* data = (const float*)d_in[0];
    const float* x    = (const float*)d_in[1];
    const float* a    = (const float*)d_in[2];
    const float* b    = (const float*)d_in[3];
    float* out        = (float*)d_out;

    int K = in_sizes[1];
    if (K > KMAX) K = KMAX;
    long long n = (long long)out_size;

    cudaFuncSetAttribute(lut_kernel,
                         cudaFuncAttributeMaxDynamicSharedMemorySize,
                         SMEM_BYTES);

    const int threads = 512;
    int blocks = 304;  // 2 CTAs per SM on 152 SMs
    long long need = (n / 4 + threads - 1) / threads;
    if ((long long)blocks > need && need > 0) blocks = (int)need;
    if (blocks < 1) blocks = 1;

    lut_kernel<<<blocks, threads, SMEM_BYTES>>>(data, x, a, b, out, K, n);
}

// round 7
// speedup vs baseline: 1.2626x; 1.2626x over previous
#include <cuda_runtime.h>
#include <cuda_bf16.h>
#include <stdint.h>

// LUT_82085414961764: out = a[idx]*d + b[idx], idx = searchsorted(x, d, 'left')
// R6: R4's bucket scheme (best: 162us) at FULL occupancy (4 CTAs/SM, 64 warps).
//   - x_s[1025]          : breakpoints + +inf sentinel (scan fallback)
//   - ab_s[1025] float2  : interleaved (a,b), single LDS.64 gather
//   - bins_s[8192] u16   : {start index (15b) | has-breakpoints flag (1b)}
// Bin function g() is the IDENTICAL monotone float expression at build and
// query time, so `start` is a provably correct lower bound for the scan.

#define KMAX 1024
#define NB   8192

__global__ __launch_bounds__(512, 4)
void lut_kernel(const float* __restrict__ data,
                const float* __restrict__ x,
                const float* __restrict__ a,
                const float* __restrict__ b,
                float* __restrict__ out,
                int K, long long n)
{
    __shared__ float    x_s[KMAX + 1];
    __shared__ float2   ab_s[KMAX + 1];
    __shared__ uint16_t bins_s[NB];

    const int tid = threadIdx.x;
    const int bd  = blockDim.x;

    // ---- build phase ----------------------------------------------------
    for (int i = tid; i < K; i += bd)  x_s[i] = x[i];
    for (int i = tid; i <= K; i += bd) ab_s[i] = make_float2(a[i], b[i]);
    if (tid == 0) x_s[K] = __int_as_float(0x7F800000);  // +inf sentinel
    __syncthreads();

    const float LO    = x_s[0];
    const float span  = x_s[K - 1] - LO;
    const float scale = (span > 0.0f) ? ((float)NB / span) : 0.0f;
    const float NBf   = (float)NB;

    // monotone bin function — identical expression at build and query
    auto g = [&](float v) -> int {
        float t = (v - LO) * scale;
        if (t < 0.0f) return 0;
        if (t >= NBf) return NB - 1;
        return (int)t;
    };

    // bins_s[bin] = (first i with g(x_s[i]) >= bin) | (flag<<15)
    for (int bin = tid; bin < NB; bin += bd) {
        int lo = 0, hi = K;
        while (lo < hi) {
            int mid = (lo + hi) >> 1;
            if (g(x_s[mid]) < bin) lo = mid + 1; else hi = mid;
        }
        unsigned flag = (lo < K && g(x_s[lo]) == bin) ? 0x8000u : 0u;
        bins_s[bin] = (uint16_t)((unsigned)lo | flag);
    }
    __syncthreads();

    // ---- streaming phase -------------------------------------------------
    auto lut1 = [&](float d) -> float {
        float t = (d - LO) * scale;
        int bin;
        if (t < 0.0f)      bin = 0;
        else if (t >= NBf) bin = NB - 1;
        else               bin = (int)t;
        unsigned v = bins_s[bin];
        int idx = (int)(v & 0x7FFFu);
        if (v & 0x8000u) {
            // forward scan; x_s[K] = +inf terminates without a bounds check
            while (x_s[idx] < d) ++idx;
        }
        float2 ab = ab_s[idx];
        return fmaf(ab.x, d, ab.y);
    };

    const long long n4 = n >> 2;
    const float4* __restrict__ in4  = (const float4*)data;
    float4* __restrict__       out4 = (float4*)out;
    const long long stride = (long long)gridDim.x * bd;

    for (long long i = (long long)blockIdx.x * bd + tid; i < n4; i += stride) {
        float4 v = in4[i];
        float4 r;
        r.x = lut1(v.x);
        r.y = lut1(v.y);
        r.z = lut1(v.z);
        r.w = lut1(v.w);
        out4[i] = r;
    }

    // tail (n not divisible by 4)
    for (long long i = (n4 << 2) + (long long)blockIdx.x * bd + tid; i < n;
         i += stride) {
        out[i] = lut1(data[i]);
    }
}

extern "C" void kernel_launch(void* const* d_in, const int* in_sizes, int n_in,
                              void* d_out, int out_size)
{
    const float* data = (const float*)d_in[0];
    const float* x    = (const float*)d_in[1];
    const float* a    = (const float*)d_in[2];
    const float* b    = (const float*)d_in[3];
    float* out        = (float*)d_out;

    int K = in_sizes[1];
    if (K > KMAX) K = KMAX;  // problem constant is 1024
    long long n = (long long)out_size;

    const int threads = 512;
    int blocks = 608;  // 4 CTAs per SM on 152 SMs
    long long need = (n / 4 + threads - 1) / threads;
    if ((long long)blocks > need && need > 0) blocks = (int)need;
    if (blocks < 1) blocks = 1;

    lut_kernel<<<blocks, threads>>>(data, x, a, b, out, K, n);
}